// round 10
// baseline (speedup 1.0000x reference)
#include <cuda_runtime.h>

// Problem constants
#define PLANE (8*16*128*128)   // floats per [B=8,C=16,H=128,W=128] stream

// Ping-pong stream buffers: [parity][row][stream(right,up,down)]
__device__ float g_buf[2u*4u*3u*(unsigned)PLANE];

// Per-tile completion flags: [cell 0..15][tile 0..511], epoch-tagged (no resets).
__device__ volatile unsigned g_flag[16 * 512];
__device__ unsigned long long g_launch_ctr = 0;   // epoch derivation

// Dynamic smem:
//   s_in : 16 ch x 18x18 halo tile, DUPLICATED float2{v,v}   41472 B
//   s_w  : per-chunk weights [cil=16][k=9][co=48]            27648 B
#define SMEM_IN_F2 (16 * 324)
#define SMEM_W_F   (16 * 9 * 48)
#define SMEM_TOTAL (SMEM_IN_F2 * 8 + SMEM_W_F * 4)

// Cells in topological (wavefront-level) order; level f = 2*col + row.
__constant__ int Tc[16] = {0,0,0,1,0,1,1,2,1,2,2,3,2,3,3,3};
__constant__ int Tr[16] = {0,1,2,0,3,1,2,0,3,1,2,0,3,1,2,3};

__device__ __forceinline__ float* BUF(int par, int row, int st) {
    return g_buf + (((size_t)par * 4 + row) * 3 + st) * (size_t)PLANE;
}

// Persistent dataflow kernel: one global job list (cell-topo-order x 512 tiles),
// static stride across CTAs. Each job spin-waits on the 3x3 producer-tile flags
// of its (up to 3) input streams, computes the conv tile, stores, then flags.
// 256 threads = 4 out-channel-groups(12 co) x 64 pixel slots (2x2 px).
__global__ __launch_bounds__(256, 2) void encoder_persistent(
    const float* __restrict__ x, const float* __restrict__ W,
    const float* __restrict__ bias, float* __restrict__ out)
{
    extern __shared__ __align__(16) float smem[];
    float2* s_in = reinterpret_cast<float2*>(smem);       // SMEM_IN_F2 float2
    float*  s_w  = smem + SMEM_IN_F2 * 2;                 // SMEM_W_F floats

    __shared__ unsigned s_epoch;
    const int tid = threadIdx.x;
    if (tid == 0) {
        unsigned long long v = atomicAdd(&g_launch_ctr, 1ull);
        s_epoch = (unsigned)(v / gridDim.x) + 1u;   // same for all CTAs of a launch
    }
    __syncthreads();
    const unsigned epoch = s_epoch;

    const int cog = tid & 3;
    const int ps  = tid >> 2;
    const int py0 = (ps >> 3) << 1, px0 = (ps & 7) << 1;
    const int cobase = cog * 12;

    #pragma unroll 1
    for (int j = blockIdx.x; j < 16 * 512; j += gridDim.x) {
        const int pos = j >> 9;
        const int t   = j & 511;
        const int c = Tc[pos], r = Tr[pos];
        const int p = c & 1, q = p ^ 1;
        const int bz = t >> 6, ty = (t >> 3) & 7, tx = t & 7;
        const int gy0 = ty << 4, gx0 = tx << 4;

        // ---- input streams + producer cell ids (mirrors reference wavefront) ----
        const float *i0 = nullptr, *i1 = nullptr, *i2 = nullptr;
        int pr0 = -1, pr1 = -1, pr2 = -1;
        if (c == 0) {
            if (r == 0) { i0 = x; }
            else        { i0 = BUF(p, r - 1, 2); pr0 = r - 1; }
        } else {
            i0 = BUF(q, r, 0); pr0 = (c - 1) * 4 + r;
            if (r == 0)      { i1 = BUF(q, 1, 1); pr1 = (c - 1) * 4 + 1; }
            else if (r == 3) { i1 = BUF(p, 2, 2); pr1 = c * 4 + 2; }
            else { i1 = BUF(q, r + 1, 1); pr1 = (c - 1) * 4 + (r + 1);
                   i2 = BUF(p, r - 1, 2); pr2 = c * 4 + (r - 1); }
        }
        float* oR = (c == 3 && r == 3) ? out : BUF(p, r, 0);
        float* oU = BUF(p, r, 1);
        float* oD = BUF(p, r, 2);
        const float* Wcell = W + (size_t)(c * 4 + r) * (48 * 48 * 9);
        const float* bc = bias + (c * 4 + r) * 48;
        const float* srcs[3] = {i0, i1, i2};
        const int prods[3] = {pr0, pr1, pr2};

        // ---- wait for producer tiles: 3x3 neighborhood per stream, parallel spin ----
        if (tid < 27) {
            const int s = tid / 9, d = tid - s * 9;
            const int pc = prods[s];
            if (pc >= 0) {
                const int ny = ty + d / 3 - 1, nx = tx + (d % 3) - 1;
                if ((unsigned)ny < 8u && (unsigned)nx < 8u) {
                    const int fi = pc * 512 + bz * 64 + ny * 8 + nx;
                    while (g_flag[fi] < epoch) __nanosleep(64);
                }
            }
        }
        __syncthreads();
        __threadfence();   // acquire: order flag observation before data reads

        // ---- conv for this tile ----
        unsigned long long acc[6][2][2];
        #pragma unroll
        for (int jp = 0; jp < 6; jp++)
            #pragma unroll
            for (int py = 0; py < 2; py++)
                #pragma unroll
                for (int px = 0; px < 2; px++)
                    acc[jp][py][px] = 0ull;

        #pragma unroll 1
        for (int chunk = 0; chunk < 3; chunk++) {
            const float* src = srcs[chunk];
            if (!src) continue;   // zero slot: skip (uniform)

            // input tile (16ch x 18x18, SAME halo), stored duplicated {v,v}
            for (int e = tid; e < 16 * 324; e += 256) {
                int ci = e / 324; int rr = e - ci * 324;
                int tyy = rr / 18; int txx = rr - tyy * 18;
                int gy = gy0 - 1 + tyy, gx = gx0 - 1 + txx;
                float v = 0.f;
                if ((unsigned)gy < 128u && (unsigned)gx < 128u)
                    v = __ldcg(&src[((bz * 16 + ci) * 128 + gy) * 128 + gx]);
                s_in[e] = make_float2(v, v);
            }
            // per-chunk weights, transposed to [cil][k][co]
            for (int e = tid; e < 16 * 432; e += 256) {
                int co = e / 144; int rr = e - co * 144;
                int cil = rr / 9; int k  = rr - cil * 9;
                s_w[(cil * 9 + k) * 48 + co] =
                    Wcell[(co * 48 + chunk * 16 + cil) * 9 + k];
            }
            __syncthreads();

            #pragma unroll 4
            for (int cil = 0; cil < 16; cil++) {
                // 4x4 patch of dup-pairs: 16 plain LDS.64, no MOV duplication
                unsigned long long xp[16];
                const unsigned long long* base =
                    reinterpret_cast<const unsigned long long*>(
                        &s_in[cil * 324 + py0 * 18 + px0]);
                #pragma unroll
                for (int dy = 0; dy < 4; dy++)
                    #pragma unroll
                    for (int dx = 0; dx < 4; dx++)
                        xp[dy * 4 + dx] = base[dy * 18 + dx];
                #pragma unroll
                for (int k = 0; k < 9; k++) {
                    const int ky = k / 3, kx = k - ky * 3;
                    const unsigned long long* wrow =
                        reinterpret_cast<const unsigned long long*>(
                            &s_w[(cil * 9 + k) * 48 + cobase]);
                    #pragma unroll
                    for (int jp = 0; jp < 6; jp++) {
                        unsigned long long w = wrow[jp];   // LDS.64 co-pair
                        #pragma unroll
                        for (int py = 0; py < 2; py++)
                            #pragma unroll
                            for (int px = 0; px < 2; px++)
                                asm("fma.rn.f32x2 %0, %1, %2, %0;"
                                    : "+l"(acc[jp][py][px])
                                    : "l"(w), "l"(xp[(py + ky) * 4 + (px + kx)]));
                    }
                }
            }
            __syncthreads();
        }

        // ---- epilogue: bias + relu; paired STG.64 over adjacent px ----
        float* outs[3] = {oR, oU, oD};
        #pragma unroll
        for (int jp = 0; jp < 6; jp++) {
            int co0 = cobase + jp * 2;
            float b0 = bc[co0], b1 = bc[co0 + 1];
            int s0 = co0 >> 4, ch0 = co0 & 15;
            float* o = outs[s0];
            #pragma unroll
            for (int py = 0; py < 2; py++) {
                float lo0, hi0, lo1, hi1;
                asm("mov.b64 {%0, %1}, %2;" : "=f"(lo0), "=f"(hi0) : "l"(acc[jp][py][0]));
                asm("mov.b64 {%0, %1}, %2;" : "=f"(lo1), "=f"(hi1) : "l"(acc[jp][py][1]));
                lo0 = fmaxf(lo0 + b0, 0.f); lo1 = fmaxf(lo1 + b0, 0.f);
                hi0 = fmaxf(hi0 + b1, 0.f); hi1 = fmaxf(hi1 + b1, 0.f);
                int gy = gy0 + py0 + py, gx = gx0 + px0;
                *reinterpret_cast<float2*>(&o[((bz * 16 + ch0)     * 128 + gy) * 128 + gx])
                    = make_float2(lo0, lo1);
                *reinterpret_cast<float2*>(&o[((bz * 16 + ch0 + 1) * 128 + gy) * 128 + gx])
                    = make_float2(hi0, hi1);
            }
        }

        // ---- publish: all stores visible, then flag this tile ----
        __threadfence();
        __syncthreads();
        if (tid == 0) g_flag[(c * 4 + r) * 512 + t] = epoch;
    }
}

extern "C" void kernel_launch(void* const* d_in, const int* in_sizes, int n_in,
                              void* d_out, int out_size)
{
    const float* x = (const float*)d_in[0];            // [8,16,128,128]
    const float* W = (const float*)d_in[1];            // [4,4,48,48,3,3]
    const float* b = (const float*)d_in[2];            // [4,4,48]
    float* out = (float*)d_out;                        // [8,16,128,128]

    // Sized once on the (uncaptured) correctness run; constant thereafter.
    static int nblocks = 0;
    if (!nblocks) {
        cudaFuncSetAttribute(encoder_persistent,
                             cudaFuncAttributeMaxDynamicSharedMemorySize, SMEM_TOTAL);
        int dev = 0; cudaGetDevice(&dev);
        int sms = 0; cudaDeviceGetAttribute(&sms, cudaDevAttrMultiProcessorCount, dev);
        int occ = 0;
        cudaOccupancyMaxActiveBlocksPerMultiprocessor(&occ, encoder_persistent,
                                                      256, SMEM_TOTAL);
        if (occ < 1) occ = 1;
        if (occ > 2) occ = 2;               // 2 CTAs/SM is the design point
        nblocks = sms * occ;                // all CTAs resident -> dataflow is safe
    }

    encoder_persistent<<<nblocks, 256, SMEM_TOTAL>>>(x, W, b, out);
}

// round 13
// speedup vs baseline: 1.0059x; 1.0059x over previous
#include <cuda_runtime.h>

// Problem constants
#define PLANE (8*16*128*128)   // floats per [B=8,C=16,H=128,W=128] stream

// Ping-pong stream buffers: [parity][row][stream(right,up,down)]
__device__ float g_buf[2u*4u*3u*(unsigned)PLANE];

// Grid barrier state (generation-based; g_count self-resets each barrier)
__device__ unsigned g_count = 0;
__device__ volatile unsigned g_gen = 0;

// Dynamic smem: input tile + FULL per-cell weight block
//   s_in : 16 ch x 18x18 halo tile                 20736 B
//   s_w  : [ci=48][k=9][co=48] transposed weights  82944 B
#define SMEM_IN_FLOATS (16 * 324)
#define SMEM_W_FLOATS  (48 * 9 * 48)
#define SMEM_TOTAL     ((SMEM_IN_FLOATS + SMEM_W_FLOATS) * 4)

__device__ __forceinline__ float* BUF(int par, int row, int st) {
    return g_buf + (((size_t)par * 4 + row) * 3 + st) * (size_t)PLANE;
}

__device__ __forceinline__ void grid_barrier(unsigned target) {
    __syncthreads();
    if (threadIdx.x == 0) {
        __threadfence();                       // release
        if (atomicAdd(&g_count, 1u) == gridDim.x - 1) {
            g_count = 0;
            __threadfence();
            g_gen = target;
        } else {
            while (g_gen != target) __nanosleep(128);
        }
        __threadfence();                       // acquire
    }
    __syncthreads();
}

// Per-level tables: first cell's column, #cells, chunk-count weights.
__constant__ int L_cmin[10]  = {0,0,0,0,1,1,2,2,3,3};
__constant__ int L_ncell[10] = {1,1,2,2,2,2,2,2,1,1};
__constant__ int L_w0[10]    = {1,1,1,1,3,2,3,2,3,2};
__constant__ int L_w1[10]    = {0,0,2,3,2,3,2,3,0,0};

// Load one 6-float patch row (3x LDS.64) and dup each float into a f32x2 reg.
#define LOADROW(dst, rowptr) do {                                           \
    const float2* _rp = reinterpret_cast<const float2*>(rowptr);            \
    float2 _a = _rp[0], _b = _rp[1], _c = _rp[2];                           \
    asm("mov.b64 %0, {%1, %1};" : "=l"(dst[0]) : "f"(_a.x));                \
    asm("mov.b64 %0, {%1, %1};" : "=l"(dst[1]) : "f"(_a.y));                \
    asm("mov.b64 %0, {%1, %1};" : "=l"(dst[2]) : "f"(_b.x));                \
    asm("mov.b64 %0, {%1, %1};" : "=l"(dst[3]) : "f"(_b.y));                \
    asm("mov.b64 %0, {%1, %1};" : "=l"(dst[4]) : "f"(_c.x));                \
    asm("mov.b64 %0, {%1, %1};" : "=l"(dst[5]) : "f"(_c.y));                \
} while (0)

// One ky slab: 3 kx * 3 co-pairs * (2 rows x 4 px) = 72 FFMA2
#define KYSLAB(ky, rlo, rhi) do {                                           \
    _Pragma("unroll")                                                       \
    for (int kx = 0; kx < 3; kx++) {                                        \
        const unsigned long long* wrow =                                    \
            reinterpret_cast<const unsigned long long*>(                    \
                &s_w[(ci * 9 + (ky) * 3 + kx) * 48 + cobase]);              \
        _Pragma("unroll")                                                   \
        for (int jp = 0; jp < 3; jp++) {                                    \
            unsigned long long w = wrow[jp];                                \
            _Pragma("unroll")                                               \
            for (int px = 0; px < 4; px++) {                                \
                asm("fma.rn.f32x2 %0, %1, %2, %0;"                          \
                    : "+l"(acc[jp][0][px]) : "l"(w), "l"(rlo[px + kx]));    \
                asm("fma.rn.f32x2 %0, %1, %2, %0;"                          \
                    : "+l"(acc[jp][1][px]) : "l"(w), "l"(rhi[px + kx]));    \
            }                                                               \
        }                                                                   \
    }                                                                       \
} while (0)

// Persistent wavefront kernel (R8 scheduling). NEW compute layout:
// 256 threads = 8 co-groups(6 co) x 32 pixel slots (2 high x 4 wide px).
// Each weight pair feeds 8 pixels -> 27 w-LDS.64 + 12 patch-LDS.64 per ci.
__global__ __launch_bounds__(256, 2) void encoder_persistent(
    const float* __restrict__ x, const float* __restrict__ W,
    const float* __restrict__ bias, float* __restrict__ out)
{
    extern __shared__ __align__(16) float smem[];
    float* s_in = smem;                    // SMEM_IN_FLOATS
    float* s_w  = smem + SMEM_IN_FLOATS;   // SMEM_W_FLOATS

    const int tid = threadIdx.x;
    const int cog8 = tid & 7;              // 8 co-groups of 6 channels
    const int ps   = tid >> 3;             // 32 pixel slots
    const int py0  = (ps >> 2) << 1;       // 0..14 step 2
    const int px0  = (ps & 3) << 2;        // 0,4,8,12
    const int cobase = cog8 * 6;

    unsigned gen = g_gen;

    #pragma unroll 1
    for (int lvl = 0; lvl < 10; lvl++) {
        // ---- work-balanced CTA partition across this level's cells ----
        int cell_sel, local_id, nlocal;
        if (L_ncell[lvl] == 2) {
            const int w0 = L_w0[lvl], wt = w0 + L_w1[lvl];
            const int n0 = (int)(((long long)gridDim.x * w0 + (wt >> 1)) / wt);
            cell_sel = (blockIdx.x >= n0) ? 1 : 0;
            local_id = blockIdx.x - cell_sel * n0;
            nlocal   = cell_sel ? (gridDim.x - n0) : n0;
        } else {
            cell_sel = 0; local_id = blockIdx.x; nlocal = gridDim.x;
        }
        const int c = L_cmin[lvl] + cell_sel;
        const int r = lvl - 2 * c;
        const int p = c & 1, q = p ^ 1;

        // ---- per-cell input/output pointers (mirrors reference wavefront) ----
        const float *i0, *i1 = nullptr, *i2 = nullptr;
        if (c == 0) {
            i0 = (r == 0) ? x : BUF(p, r - 1, 2);
        } else {
            i0 = BUF(q, r, 0);
            if (r == 0)      i1 = BUF(q, 1, 1);
            else if (r == 3) i1 = BUF(p, 2, 2);
            else { i1 = BUF(q, r + 1, 1); i2 = BUF(p, r - 1, 2); }
        }
        float* oR = (c == 3 && r == 3) ? out : BUF(p, r, 0);
        float* oU = BUF(p, r, 1);
        float* oD = BUF(p, r, 2);
        const float* Wc = W + (size_t)(c * 4 + r) * (48 * 48 * 9);
        const float* bc = bias + (c * 4 + r) * 48;
        const float* srcs[3] = {i0, i1, i2};

        // ---- load FULL weight block for this cell, transposed to [ci][k][co] ----
        for (int e = tid; e < 48 * 432; e += 256) {
            int co = e / 432; int rr = e - co * 432;
            int ci = rr / 9;  int k  = rr - ci * 9;
            s_w[(ci * 9 + k) * 48 + co] = Wc[(co * 48 + ci) * 9 + k];
        }

        // ---- sweep this CTA's tiles of the cell ----
        #pragma unroll 1
        for (int t = local_id; t < 512; t += nlocal) {
            const int bz  = t >> 6;
            const int gy0 = ((t >> 3) & 7) << 4;
            const int gx0 = (t & 7) << 4;

            unsigned long long acc[3][2][4];
            #pragma unroll
            for (int jp = 0; jp < 3; jp++)
                #pragma unroll
                for (int py = 0; py < 2; py++)
                    #pragma unroll
                    for (int px = 0; px < 4; px++)
                        acc[jp][py][px] = 0ull;

            #pragma unroll 1
            for (int chunk = 0; chunk < 3; chunk++) {
                const float* src = srcs[chunk];
                if (!src) continue;   // zero slot: skip (uniform)

                // input tile (16ch x 18x18, SAME halo) — plain f32, L2-direct
                for (int e = tid; e < 16 * 324; e += 256) {
                    int cc = e / 324; int rr = e - cc * 324;
                    int ty = rr / 18; int tx = rr - ty * 18;
                    int gy = gy0 - 1 + ty, gx = gx0 - 1 + tx;
                    float v = 0.f;
                    if ((unsigned)gy < 128u && (unsigned)gx < 128u)
                        v = __ldcg(&src[((bz * 16 + cc) * 128 + gy) * 128 + gx]);
                    s_in[e] = v;
                }
                __syncthreads();

                #pragma unroll 1
                for (int cil = 0; cil < 16; cil++) {
                    const int ci = chunk * 16 + cil;    // global input channel
                    const float* base = &s_in[cil * 324 + py0 * 18 + px0];

                    // ky-windowed dup rows (full unroll -> renaming, no shifts)
                    unsigned long long r0[6], r1[6], r2[6], r3[6];
                    LOADROW(r0, base);
                    LOADROW(r1, base + 18);
                    KYSLAB(0, r0, r1);
                    LOADROW(r2, base + 36);
                    KYSLAB(1, r1, r2);
                    LOADROW(r3, base + 54);
                    KYSLAB(2, r2, r3);
                }
                __syncthreads();
            }

            // ---- epilogue: bias + relu; STG.128 across the 4 contiguous px ----
            float* outs[3] = {oR, oU, oD};
            #pragma unroll
            for (int jp = 0; jp < 3; jp++) {
                int co0 = cobase + jp * 2;
                float b0 = bc[co0], b1 = bc[co0 + 1];
                int s0 = co0 >> 4, ch0 = co0 & 15;
                float* o = outs[s0];
                #pragma unroll
                for (int py = 0; py < 2; py++) {
                    float lo[4], hi[4];
                    #pragma unroll
                    for (int px = 0; px < 4; px++) {
                        float l, h;
                        asm("mov.b64 {%0, %1}, %2;" : "=f"(l), "=f"(h)
                            : "l"(acc[jp][py][px]));
                        lo[px] = fmaxf(l + b0, 0.f);
                        hi[px] = fmaxf(h + b1, 0.f);
                    }
                    int gy = gy0 + py0 + py, gx = gx0 + px0;
                    *reinterpret_cast<float4*>(&o[((bz * 16 + ch0) * 128 + gy) * 128 + gx])
                        = make_float4(lo[0], lo[1], lo[2], lo[3]);
                    *reinterpret_cast<float4*>(&o[((bz * 16 + ch0 + 1) * 128 + gy) * 128 + gx])
                        = make_float4(hi[0], hi[1], hi[2], hi[3]);
                }
            }
        }

        if (lvl < 9) { ++gen; grid_barrier(gen); }
    }
}

extern "C" void kernel_launch(void* const* d_in, const int* in_sizes, int n_in,
                              void* d_out, int out_size)
{
    const float* x = (const float*)d_in[0];            // [8,16,128,128]
    const float* W = (const float*)d_in[1];            // [4,4,48,48,3,3]
    const float* b = (const float*)d_in[2];            // [4,4,48]
    float* out = (float*)d_out;                        // [8,16,128,128]

    static int nblocks = 0;
    if (!nblocks) {
        cudaFuncSetAttribute(encoder_persistent,
                             cudaFuncAttributeMaxDynamicSharedMemorySize, SMEM_TOTAL);
        int dev = 0; cudaGetDevice(&dev);
        int sms = 0; cudaDeviceGetAttribute(&sms, cudaDevAttrMultiProcessorCount, dev);
        int occ = 0;
        cudaOccupancyMaxActiveBlocksPerMultiprocessor(&occ, encoder_persistent,
                                                      256, SMEM_TOTAL);
        if (occ < 1) occ = 1;
        if (occ > 2) occ = 2;               // 2 CTAs/SM is the design point
        nblocks = sms * occ;                // all CTAs resident -> barrier is safe
    }

    encoder_persistent<<<nblocks, 256, SMEM_TOTAL>>>(x, W, b, out);
}

// round 15
// speedup vs baseline: 1.0447x; 1.0386x over previous
#include <cuda_runtime.h>

// Problem constants
#define PLANE (8*16*128*128)   // floats per [B=8,C=16,H=128,W=128] stream

// Ping-pong stream buffers: [parity][row][stream(right,up,down)]
__device__ float g_buf[2u*4u*3u*(unsigned)PLANE];

// Grid barrier state (generation-based; g_count self-resets each barrier)
__device__ unsigned g_count = 0;
__device__ volatile unsigned g_gen = 0;

// Dynamic smem: double-buffered chunk staging
//   s_in[2] : 16 ch x 18x18 halo tile        2 x 20736 B
//   s_w [2] : [cil=16][k=9][co=48] weights   2 x 27648 B
#define IN_F 5184                  // 16*324
#define W_F  6912                  // 16*9*48
#define SMEM_TOTAL ((2*IN_F + 2*W_F) * 4)   // 96768 B -> 2 CTAs/SM

__device__ __forceinline__ float* BUF(int par, int row, int st) {
    return g_buf + (((size_t)par * 4 + row) * 3 + st) * (size_t)PLANE;
}

__device__ __forceinline__ void grid_barrier(unsigned target) {
    __syncthreads();
    if (threadIdx.x == 0) {
        __threadfence();                       // release (+ L1 inval on sm_103a)
        if (atomicAdd(&g_count, 1u) == gridDim.x - 1) {
            g_count = 0;
            __threadfence();
            g_gen = target;
        } else {
            while (g_gen != target) __nanosleep(128);
        }
        __threadfence();                       // acquire (+ L1 inval)
    }
    __syncthreads();
}

// cp.async helpers (4-byte, L1-cached path; sz=0 -> zero-fill)
__device__ __forceinline__ void cp4(unsigned dst, const void* src, unsigned sz) {
    asm volatile("cp.async.ca.shared.global [%0], [%1], 4, %2;"
                 :: "r"(dst), "l"(src), "r"(sz) : "memory");
}
#define CP_COMMIT() asm volatile("cp.async.commit_group;" ::: "memory")
#define CP_WAIT0()  asm volatile("cp.async.wait_group 0;" ::: "memory")

// Per-level tables: first cell's column, #cells, chunk-count weights.
__constant__ int L_cmin[10]  = {0,0,0,0,1,1,2,2,3,3};
__constant__ int L_ncell[10] = {1,1,2,2,2,2,2,2,1,1};
__constant__ int L_w0[10]    = {1,1,1,1,3,2,3,2,3,2};
__constant__ int L_w1[10]    = {0,0,2,3,2,3,2,3,0,0};

// Persistent wavefront kernel (R8 scheduling) + cp.async double-buffered chunk
// pipeline: while chunk j is computed, chunk j+1 (or next tile's first chunk)
// streams into the other buffer. One __syncthreads per chunk.
// 256 threads = 4 out-channel-groups(12 co) x 64 pixel slots (2x2 px).
__global__ __launch_bounds__(256, 2) void encoder_persistent(
    const float* __restrict__ x, const float* __restrict__ W,
    const float* __restrict__ bias, float* __restrict__ out)
{
    extern __shared__ __align__(16) float smem[];
    // buffers: s_in b at smem + b*IN_F ; s_w b at smem + 2*IN_F + b*W_F

    const int tid = threadIdx.x;
    const int cog = tid & 3;
    const int ps  = tid >> 2;
    const int py0 = (ps >> 3) << 1, px0 = (ps & 7) << 1;
    const int cobase = cog * 12;

    const unsigned smem_u32 = (unsigned)__cvta_generic_to_shared(smem);

    unsigned gen = g_gen;
    unsigned bctr = 0;   // global chunk counter -> buffer rotation

    #pragma unroll 1
    for (int lvl = 0; lvl < 10; lvl++) {
        // ---- work-balanced CTA partition across this level's cells ----
        int cell_sel, local_id, nlocal;
        if (L_ncell[lvl] == 2) {
            const int w0 = L_w0[lvl], wt = w0 + L_w1[lvl];
            const int n0 = (int)(((long long)gridDim.x * w0 + (wt >> 1)) / wt);
            cell_sel = (blockIdx.x >= n0) ? 1 : 0;
            local_id = blockIdx.x - cell_sel * n0;
            nlocal   = cell_sel ? ((int)gridDim.x - n0) : n0;
        } else {
            cell_sel = 0; local_id = blockIdx.x; nlocal = gridDim.x;
        }
        const int c = L_cmin[lvl] + cell_sel;
        const int r = lvl - 2 * c;
        const int p = c & 1, q = p ^ 1;

        // ---- per-cell input/output pointers (mirrors reference wavefront) ----
        const float *i0, *i1 = nullptr, *i2 = nullptr;
        if (c == 0) {
            i0 = (r == 0) ? x : BUF(p, r - 1, 2);
        } else {
            i0 = BUF(q, r, 0);
            if (r == 0)      i1 = BUF(q, 1, 1);
            else if (r == 3) i1 = BUF(p, 2, 2);
            else { i1 = BUF(q, r + 1, 1); i2 = BUF(p, r - 1, 2); }
        }
        float* oR = (c == 3 && r == 3) ? out : BUF(p, r, 0);
        float* oU = BUF(p, r, 1);
        float* oD = BUF(p, r, 2);
        const float* Wc = W + (size_t)(c * 4 + r) * (48 * 48 * 9);
        const float* bc = bias + (c * 4 + r) * 48;

        // active chunk list, packed in nibbles
        int cpack = 0, nck = 0;
        if (i0) { cpack |= 0 << (4 * nck); nck++; }
        if (i1) { cpack |= 1 << (4 * nck); nck++; }
        if (i2) { cpack |= 2 << (4 * nck); nck++; }

        // prefetch of (tile, chunk) into buffer b
        auto prefetch = [&](int tile, int chk, unsigned b) {
            const float* src = (chk == 0) ? i0 : ((chk == 1) ? i1 : i2);
            const int bz  = tile >> 6;
            const int gy0 = ((tile >> 3) & 7) << 4;
            const int gx0 = (tile & 7) << 4;
            const unsigned din = smem_u32 + b * (IN_F * 4);
            const unsigned dw  = smem_u32 + (2 * IN_F + b * W_F) * 4;
            // input tile: 16ch x 18x18 SAME halo (zero-fill OOB via sz=0)
            for (int e = tid; e < IN_F; e += 256) {
                int ci = e / 324; int rr = e - ci * 324;
                int ty = rr / 18;  int tx = rr - ty * 18;
                int gy = gy0 - 1 + ty, gx = gx0 - 1 + tx;
                bool ok = ((unsigned)gy < 128u) & ((unsigned)gx < 128u);
                const float* g = ok ? &src[((bz * 16 + ci) * 128 + gy) * 128 + gx] : src;
                cp4(din + e * 4, g, ok ? 4u : 0u);
            }
            // chunk weights, transposed to [cil][k][co]
            for (int e = tid; e < W_F; e += 256) {
                int co = e / 144; int rr = e - co * 144;
                int ci = rr / 9;  int k  = rr - ci * 9;
                cp4(dw + ((ci * 9 + k) * 48 + co) * 4,
                    &Wc[(co * 48 + chk * 16 + ci) * 9 + k], 4u);
            }
        };

        // ---- pipelined tile sweep ----
        int t = local_id;
        if (t < 512) { prefetch(t, cpack & 15, bctr & 1); CP_COMMIT(); }

        #pragma unroll 1
        for (; t < 512; t += nlocal) {
            const int bz  = t >> 6;
            const int gy0 = ((t >> 3) & 7) << 4;
            const int gx0 = (t & 7) << 4;

            unsigned long long acc[6][2][2];
            #pragma unroll
            for (int jp = 0; jp < 6; jp++)
                #pragma unroll
                for (int py = 0; py < 2; py++)
                    #pragma unroll
                    for (int px = 0; px < 2; px++)
                        acc[jp][py][px] = 0ull;

            #pragma unroll 1
            for (int i = 0; i < nck; i++) {
                CP_WAIT0();
                __syncthreads();      // buffer (bctr&1) ready; buffer (bctr+1)&1 free

                // issue next prefetch (next chunk, or next tile's first chunk)
                int nt, nc;
                if (i + 1 < nck) { nt = t; nc = (cpack >> (4 * (i + 1))) & 15; }
                else             { nt = t + nlocal; nc = cpack & 15; }
                if (nt < 512) { prefetch(nt, nc, (bctr + 1) & 1); CP_COMMIT(); }

                // compute from buffer bctr&1
                const float* sin_b = smem + (bctr & 1) * IN_F;
                const float* sw_b  = smem + 2 * IN_F + (bctr & 1) * W_F;
                #pragma unroll 4
                for (int ci = 0; ci < 16; ci++) {
                    unsigned long long xp[16];
                    const float* base = &sin_b[ci * 324 + py0 * 18 + px0];
                    #pragma unroll
                    for (int dy = 0; dy < 4; dy++)
                        #pragma unroll
                        for (int dx = 0; dx < 4; dx++) {
                            float v = base[dy * 18 + dx];
                            asm("mov.b64 %0, {%1, %1};" : "=l"(xp[dy * 4 + dx]) : "f"(v));
                        }
                    #pragma unroll
                    for (int k = 0; k < 9; k++) {
                        const int ky = k / 3, kx = k - ky * 3;
                        const unsigned long long* wrow =
                            reinterpret_cast<const unsigned long long*>(
                                &sw_b[(ci * 9 + k) * 48 + cobase]);
                        #pragma unroll
                        for (int jp = 0; jp < 6; jp++) {
                            unsigned long long w = wrow[jp];   // LDS.64 co-pair
                            #pragma unroll
                            for (int py = 0; py < 2; py++)
                                #pragma unroll
                                for (int px = 0; px < 2; px++)
                                    asm("fma.rn.f32x2 %0, %1, %2, %0;"
                                        : "+l"(acc[jp][py][px])
                                        : "l"(w), "l"(xp[(py + ky) * 4 + (px + kx)]));
                        }
                    }
                }
                bctr++;
            }

            // ---- epilogue: bias + relu; paired STG.64 over adjacent px ----
            float* outs[3] = {oR, oU, oD};
            #pragma unroll
            for (int jp = 0; jp < 6; jp++) {
                int co0 = cobase + jp * 2;
                float b0 = bc[co0], b1 = bc[co0 + 1];
                int s0 = co0 >> 4, ch0 = co0 & 15;
                float* o = outs[s0];
                #pragma unroll
                for (int py = 0; py < 2; py++) {
                    float lo0, hi0, lo1, hi1;
                    asm("mov.b64 {%0, %1}, %2;" : "=f"(lo0), "=f"(hi0) : "l"(acc[jp][py][0]));
                    asm("mov.b64 {%0, %1}, %2;" : "=f"(lo1), "=f"(hi1) : "l"(acc[jp][py][1]));
                    lo0 = fmaxf(lo0 + b0, 0.f); lo1 = fmaxf(lo1 + b0, 0.f);
                    hi0 = fmaxf(hi0 + b1, 0.f); hi1 = fmaxf(hi1 + b1, 0.f);
                    int gy = gy0 + py0 + py, gx = gx0 + px0;
                    *reinterpret_cast<float2*>(&o[((bz * 16 + ch0)     * 128 + gy) * 128 + gx])
                        = make_float2(lo0, lo1);
                    *reinterpret_cast<float2*>(&o[((bz * 16 + ch0 + 1) * 128 + gy) * 128 + gx])
                        = make_float2(hi0, hi1);
                }
            }
        }

        if (lvl < 9) { ++gen; grid_barrier(gen); }
    }
}

extern "C" void kernel_launch(void* const* d_in, const int* in_sizes, int n_in,
                              void* d_out, int out_size)
{
    const float* x = (const float*)d_in[0];            // [8,16,128,128]
    const float* W = (const float*)d_in[1];            // [4,4,48,48,3,3]
    const float* b = (const float*)d_in[2];            // [4,4,48]
    float* out = (float*)d_out;                        // [8,16,128,128]

    static int nblocks = 0;
    if (!nblocks) {
        cudaFuncSetAttribute(encoder_persistent,
                             cudaFuncAttributeMaxDynamicSharedMemorySize, SMEM_TOTAL);
        int dev = 0; cudaGetDevice(&dev);
        int sms = 0; cudaDeviceGetAttribute(&sms, cudaDevAttrMultiProcessorCount, dev);
        int occ = 0;
        cudaOccupancyMaxActiveBlocksPerMultiprocessor(&occ, encoder_persistent,
                                                      256, SMEM_TOTAL);
        if (occ < 1) occ = 1;
        if (occ > 2) occ = 2;               // 2 CTAs/SM is the design point
        nblocks = sms * occ;                // all CTAs resident -> barrier is safe
    }

    encoder_persistent<<<nblocks, 256, SMEM_TOTAL>>>(x, W, b, out);
}